// round 2
// baseline (speedup 1.0000x reference)
#include <cuda_runtime.h>
#include <cuda_bf16.h>
#include <math.h>

// ---------------- problem constants ----------------
#define D_BATCH 8
#define N_SEQ   2048
#define T_TOK   (D_BATCH * N_SEQ)   // 16384
#define DM      1024
#define FF      4096
#define VOCAB   32000
#define NCAT    75
#define D_HALF  512
#define LN_EPS  1e-5f

// ---------------- scratch (device globals; no allocation allowed) ----------------
__device__ float g_x  [(size_t)T_TOK * DM];
__device__ float g_q  [(size_t)T_TOK * DM];
__device__ float g_k  [(size_t)T_TOK * DM];
__device__ float g_v  [(size_t)T_TOK * DM];
__device__ float g_M  [(size_t)D_BATCH * DM * DM];   // K^T V  per batch
__device__ float g_M2 [(size_t)D_BATCH * DM * DM];   // (K^T V) Wu / 8
__device__ float g_u  [(size_t)T_TOK * DM];
__device__ float g_h1 [(size_t)T_TOK * DM];
__device__ float g_t1 [(size_t)T_TOK * FF];
__device__ float g_ffo[(size_t)T_TOK * DM];
__device__ float g_h2 [(size_t)T_TOK * DM];
__device__ float g_t3 [(size_t)T_TOK * D_HALF];
__device__ float g_lg [(size_t)T_TOK * NCAT];

// ---------------- embed + positional encoding ----------------
__global__ void embed_kernel(const int* __restrict__ idx,
                             const float* __restrict__ emb,
                             float* __restrict__ x)
{
    int row = blockIdx.x;           // token index 0..16383
    int pos = row & (N_SEQ - 1);    // position within sequence
    int t   = threadIdx.x;          // 256 threads, 4 cols each
    int id  = idx[row];
    if (id >= VOCAB || id < 0) id = 1;

    int c0 = t * 4;                 // even
    int p0 = c0 >> 1;               // pair index for cols c0,c0+1
    int p1 = p0 + 1;                // pair index for cols c0+2,c0+3

    double inv0 = pow(10000.0, -(double)p0 / 512.0);
    double inv1 = pow(10000.0, -(double)p1 / 512.0);
    float ang0 = (float)((double)pos * inv0);
    float ang1 = (float)((double)pos * inv1);
    float s0, cO0, s1, cO1;
    sincosf(ang0, &s0, &cO0);
    sincosf(ang1, &s1, &cO1);

    float4 e = *reinterpret_cast<const float4*>(emb + (size_t)id * DM + c0);
    float4 o;
    o.x = e.x + s0;
    o.y = e.y + cO0;
    o.z = e.z + s1;
    o.w = e.w + cO1;
    *reinterpret_cast<float4*>(x + (size_t)row * DM + c0) = o;
}

// ---------------- generic tiled SGEMM ----------------
// C[b] = alpha * op(A[b]) @ B[b] + bias  (optional relu)
// op(A) = A        (TRANSA=false): A is [M,K], lda = row stride
// op(A) = A^T      (TRANSA=true) : A is [K,M], lda = row stride
// B is [K,N] row-major. Batched via grid.z with element strides sA,sB,sC.
#define BM 128
#define BN 128
#define BKK 16
#define TM 8
#define TN 8

template<bool TRANSA, bool RELU>
__global__ __launch_bounds__(256)
void gemm_kernel(const float* __restrict__ A, const float* __restrict__ B,
                 const float* __restrict__ bias, float* __restrict__ C,
                 int M, int N, int K, int lda, int ldb, int ldc,
                 size_t sA, size_t sB, size_t sC, float alpha)
{
    __shared__ float As[BKK][BM];
    __shared__ float Bs[BKK][BN];

    int b = blockIdx.z;
    A += (size_t)b * sA;
    B += (size_t)b * sB;
    C += (size_t)b * sC;

    int m0 = blockIdx.y * BM;
    int n0 = blockIdx.x * BN;
    int tid = threadIdx.x;
    int tx = tid & 15;      // 0..15
    int ty = tid >> 4;      // 0..15

    float acc[TM][TN];
#pragma unroll
    for (int i = 0; i < TM; ++i)
#pragma unroll
        for (int j = 0; j < TN; ++j) acc[i][j] = 0.f;

    const bool nvec = ((N & 3) == 0);

    for (int k0 = 0; k0 < K; k0 += BKK) {
        // ---- load A tile into As[k][m] ----
        if (!TRANSA) {
#pragma unroll
            for (int it = 0; it < 2; ++it) {
                int idx4 = tid + it * 256;      // 0..511
                int row  = idx4 >> 2;           // 0..127  (m within tile)
                int kc   = (idx4 & 3) * 4;      // 0,4,8,12
                float4 av = make_float4(0.f, 0.f, 0.f, 0.f);
                int gm = m0 + row;
                if (gm < M)
                    av = *reinterpret_cast<const float4*>(A + (size_t)gm * lda + k0 + kc);
                As[kc + 0][row] = av.x;
                As[kc + 1][row] = av.y;
                As[kc + 2][row] = av.z;
                As[kc + 3][row] = av.w;
            }
        } else {
#pragma unroll
            for (int it = 0; it < 2; ++it) {
                int idx4 = tid + it * 256;
                int row  = idx4 >> 5;           // 0..15 (k within tile)
                int mc   = (idx4 & 31) * 4;     // 0..124
                const float* ap = A + (size_t)(k0 + row) * lda;
                float4 av;
                int gm = m0 + mc;
                if (gm + 3 < M) {
                    av = *reinterpret_cast<const float4*>(ap + gm);
                } else {
                    av.x = (gm + 0 < M) ? ap[gm + 0] : 0.f;
                    av.y = (gm + 1 < M) ? ap[gm + 1] : 0.f;
                    av.z = (gm + 2 < M) ? ap[gm + 2] : 0.f;
                    av.w = (gm + 3 < M) ? ap[gm + 3] : 0.f;
                }
                *reinterpret_cast<float4*>(&As[row][mc]) = av;
            }
        }
        // ---- load B tile into Bs[k][n] ----
#pragma unroll
        for (int it = 0; it < 2; ++it) {
            int idx4 = tid + it * 256;
            int row  = idx4 >> 5;               // 0..15
            int nc   = (idx4 & 31) * 4;         // 0..124
            float4 bv = make_float4(0.f, 0.f, 0.f, 0.f);
            int gn = n0 + nc;
            const float* bp = B + (size_t)(k0 + row) * ldb;
            if (nvec) {
                if (gn < N) bv = *reinterpret_cast<const float4*>(bp + gn);
            } else {
                if (gn + 0 < N) bv.x = bp[gn + 0];
                if (gn + 1 < N) bv.y = bp[gn + 1];
                if (gn + 2 < N) bv.z = bp[gn + 2];
                if (gn + 3 < N) bv.w = bp[gn + 3];
            }
            *reinterpret_cast<float4*>(&Bs[row][nc]) = bv;
        }
        __syncthreads();

#pragma unroll
        for (int kk = 0; kk < BKK; ++kk) {
            float a[TM], bb[TN];
#pragma unroll
            for (int i = 0; i < TM; ++i) a[i] = As[kk][ty * TM + i];
#pragma unroll
            for (int j = 0; j < TN; ++j) bb[j] = Bs[kk][tx * TN + j];
#pragma unroll
            for (int i = 0; i < TM; ++i)
#pragma unroll
                for (int j = 0; j < TN; ++j)
                    acc[i][j] += a[i] * bb[j];
        }
        __syncthreads();
    }

    // ---- epilogue ----
#pragma unroll
    for (int i = 0; i < TM; ++i) {
        int gm = m0 + ty * TM + i;
        if (gm >= M) continue;
        float* cp = C + (size_t)gm * ldc;
#pragma unroll
        for (int j = 0; j < TN; ++j) {
            int gn = n0 + tx * TN + j;
            if (gn >= N) continue;
            float vv = acc[i][j] * alpha;
            if (bias) vv += bias[gn];
            if (RELU) vv = fmaxf(vv, 0.f);
            cp[gn] = vv;
        }
    }
}

// ---------------- residual + layernorm over 1024 ----------------
__global__ __launch_bounds__(256)
void add_ln_kernel(const float* __restrict__ X, const float* __restrict__ U,
                   const float* __restrict__ g, const float* __restrict__ be,
                   float* __restrict__ out)
{
    __shared__ float ssum[8], ssq[8];
    __shared__ float smu, srs;
    int row = blockIdx.x;
    int t = threadIdx.x;

    float4 xv = *reinterpret_cast<const float4*>(X + (size_t)row * DM + t * 4);
    float4 uv = *reinterpret_cast<const float4*>(U + (size_t)row * DM + t * 4);
    float v0 = xv.x + uv.x, v1 = xv.y + uv.y, v2 = xv.z + uv.z, v3 = xv.w + uv.w;

    float s  = v0 + v1 + v2 + v3;
    float q  = v0 * v0 + v1 * v1 + v2 * v2 + v3 * v3;
#pragma unroll
    for (int o = 16; o; o >>= 1) {
        s += __shfl_xor_sync(0xFFFFFFFFu, s, o);
        q += __shfl_xor_sync(0xFFFFFFFFu, q, o);
    }
    int warp = t >> 5, lane = t & 31;
    if (lane == 0) { ssum[warp] = s; ssq[warp] = q; }
    __syncthreads();
    if (t == 0) {
        float S = 0.f, Q = 0.f;
#pragma unroll
        for (int i = 0; i < 8; ++i) { S += ssum[i]; Q += ssq[i]; }
        float mu = S * (1.f / DM);
        float var = Q * (1.f / DM) - mu * mu;
        smu = mu;
        srs = rsqrtf(var + LN_EPS);
    }
    __syncthreads();
    float mu = smu, rs = srs;

    float4 gv  = *reinterpret_cast<const float4*>(g  + t * 4);
    float4 bv  = *reinterpret_cast<const float4*>(be + t * 4);
    float4 o;
    o.x = (v0 - mu) * rs * gv.x + bv.x;
    o.y = (v1 - mu) * rs * gv.y + bv.y;
    o.z = (v2 - mu) * rs * gv.z + bv.z;
    o.w = (v3 - mu) * rs * gv.w + bv.w;
    *reinterpret_cast<float4*>(out + (size_t)row * DM + t * 4) = o;
}

// ---------------- final: sigmoid(layernorm(logits)) over 75 ----------------
__global__ __launch_bounds__(256)
void final_kernel(const float* __restrict__ lg,
                  const float* __restrict__ g, const float* __restrict__ be,
                  float* __restrict__ out)
{
    int row = blockIdx.x * 8 + (threadIdx.x >> 5);
    int lane = threadIdx.x & 31;
    if (row >= T_TOK) return;
    const float* lp = lg + (size_t)row * NCAT;

    float v[3];
    float s = 0.f, q = 0.f;
#pragma unroll
    for (int i = 0; i < 3; ++i) {
        int c = lane + i * 32;
        float x = (c < NCAT) ? lp[c] : 0.f;
        v[i] = x;
        s += x;
        q += x * x;
    }
#pragma unroll
    for (int o = 16; o; o >>= 1) {
        s += __shfl_xor_sync(0xFFFFFFFFu, s, o);
        q += __shfl_xor_sync(0xFFFFFFFFu, q, o);
    }
    float mu  = s * (1.f / NCAT);
    float var = q * (1.f / NCAT) - mu * mu;
    float rs  = rsqrtf(var + LN_EPS);

    float* op = out + (size_t)row * NCAT;
#pragma unroll
    for (int i = 0; i < 3; ++i) {
        int c = lane + i * 32;
        if (c < NCAT) {
            float z = (v[i] - mu) * rs * g[c] + be[c];
            op[c] = 1.f / (1.f + expf(-z));
        }
    }
}

// ---------------- host launcher ----------------
extern "C" void kernel_launch(void* const* d_in, const int* in_sizes, int n_in,
                              void* d_out, int out_size)
{
    const int*   idx = (const int*)  d_in[0];
    const float* emb = (const float*)d_in[1];
    const float* Wq  = (const float*)d_in[2];
    const float* bq  = (const float*)d_in[3];
    const float* Wk  = (const float*)d_in[4];
    const float* bk  = (const float*)d_in[5];
    const float* Wv  = (const float*)d_in[6];
    const float* bv  = (const float*)d_in[7];
    const float* Wu  = (const float*)d_in[8];
    const float* bu  = (const float*)d_in[9];
    const float* g1  = (const float*)d_in[10];
    const float* be1 = (const float*)d_in[11];
    const float* W1  = (const float*)d_in[12];
    const float* b1  = (const float*)d_in[13];
    const float* W2  = (const float*)d_in[14];
    const float* b2  = (const float*)d_in[15];
    const float* g2  = (const float*)d_in[16];
    const float* be2 = (const float*)d_in[17];
    const float* W3  = (const float*)d_in[18];
    const float* b3  = (const float*)d_in[19];
    const float* W4  = (const float*)d_in[20];
    const float* b4  = (const float*)d_in[21];
    const float* g3  = (const float*)d_in[22];
    const float* be3 = (const float*)d_in[23];
    float* out = (float*)d_out;

    float *x, *q, *k, *v, *Mb, *M2, *u, *h1, *t1, *ffo, *h2, *t3, *lg;
    cudaGetSymbolAddress((void**)&x,  g_x);
    cudaGetSymbolAddress((void**)&q,  g_q);
    cudaGetSymbolAddress((void**)&k,  g_k);
    cudaGetSymbolAddress((void**)&v,  g_v);
    cudaGetSymbolAddress((void**)&Mb, g_M);
    cudaGetSymbolAddress((void**)&M2, g_M2);
    cudaGetSymbolAddress((void**)&u,  g_u);
    cudaGetSymbolAddress((void**)&h1, g_h1);
    cudaGetSymbolAddress((void**)&t1, g_t1);
    cudaGetSymbolAddress((void**)&ffo,g_ffo);
    cudaGetSymbolAddress((void**)&h2, g_h2);
    cudaGetSymbolAddress((void**)&t3, g_t3);
    cudaGetSymbolAddress((void**)&lg, g_lg);

    // 1. x = emb[idx] + posenc
    embed_kernel<<<T_TOK, 256>>>(idx, emb, x);

    // 2-4. Q/K/V projections: [16384,1024] @ [1024,1024]
    dim3 gQKV(DM / BN, T_TOK / BM, 1);
    gemm_kernel<false,false><<<gQKV, 256>>>(x, Wq, bq, q, T_TOK, DM, DM, DM, DM, DM, 0, 0, 0, 1.f);
    gemm_kernel<false,false><<<gQKV, 256>>>(x, Wk, bk, k, T_TOK, DM, DM, DM, DM, DM, 0, 0, 0, 1.f);
    gemm_kernel<false,false><<<gQKV, 256>>>(x, Wv, bv, v, T_TOK, DM, DM, DM, DM, DM, 0, 0, 0, 1.f);

    // 5. Mb = K^T V per batch  (softmax-free attention reassociation)
    dim3 gKTV(DM / BN, DM / BM, D_BATCH);
    gemm_kernel<true,false><<<gKTV, 256>>>(k, v, nullptr, Mb, DM, DM, N_SEQ,
                                           DM, DM, DM,
                                           (size_t)N_SEQ * DM, (size_t)N_SEQ * DM,
                                           (size_t)DM * DM, 1.f);

    // 6. M2 = (Mb @ Wu) / 8  (1/sqrt(dk) folded in)
    dim3 gM2(DM / BN, DM / BM, D_BATCH);
    gemm_kernel<false,false><<<gM2, 256>>>(Mb, Wu, nullptr, M2, DM, DM, DM,
                                           DM, DM, DM,
                                           (size_t)DM * DM, 0, (size_t)DM * DM, 0.125f);

    // 7. u = Q @ M2 + bu per batch
    dim3 gU(DM / BN, N_SEQ / BM, D_BATCH);
    gemm_kernel<false,false><<<gU, 256>>>(q, M2, bu, u, N_SEQ, DM, DM,
                                          DM, DM, DM,
                                          (size_t)N_SEQ * DM, (size_t)DM * DM,
                                          (size_t)N_SEQ * DM, 1.f);

    // 8. h1 = LN(x + u)
    add_ln_kernel<<<T_TOK, 256>>>(x, u, g1, be1, h1);

    // 9. t1 = relu(h1 @ W1 + b1)   [16384,4096]
    dim3 gF1(FF / BN, T_TOK / BM, 1);
    gemm_kernel<false,true><<<gF1, 256>>>(h1, W1, b1, t1, T_TOK, FF, DM, DM, FF, FF, 0, 0, 0, 1.f);

    // 10. ffo = t1 @ W2 + b2
    dim3 gF2(DM / BN, T_TOK / BM, 1);
    gemm_kernel<false,false><<<gF2, 256>>>(t1, W2, b2, ffo, T_TOK, DM, FF, FF, DM, DM, 0, 0, 0, 1.f);

    // 11. h2 = LN(h1 + ffo)
    add_ln_kernel<<<T_TOK, 256>>>(h1, ffo, g2, be2, h2);

    // 12. t3 = relu(h2 @ W3 + b3)  [16384,512]
    dim3 gH(D_HALF / BN, T_TOK / BM, 1);
    gemm_kernel<false,true><<<gH, 256>>>(h2, W3, b3, t3, T_TOK, D_HALF, DM, DM, D_HALF, D_HALF, 0, 0, 0, 1.f);

    // 13. logits = t3 @ W4 + b4    [16384,75]
    dim3 gL((NCAT + BN - 1) / BN, T_TOK / BM, 1);
    gemm_kernel<false,false><<<gL, 256>>>(t3, W4, b4, lg, T_TOK, NCAT, D_HALF,
                                          D_HALF, NCAT, NCAT, 0, 0, 0, 1.f);

    // 14. out = sigmoid(LN(logits))
    final_kernel<<<T_TOK / 8, 256>>>(lg, g3, be3, out);
}

// round 5
// speedup vs baseline: 2.8307x; 2.8307x over previous
#include <cuda_runtime.h>
#include <cuda_bf16.h>
#include <cstdint>
#include <math.h>

// ---------------- problem constants ----------------
#define D_BATCH 8
#define N_SEQ   2048
#define T_TOK   16384
#define DM      1024
#define FF      4096
#define VOCAB   32000
#define NCAT    75
#define D_HALF  512
#define LN_EPS  1e-5f

typedef __nv_bfloat16 bf16;

// ---------------- scratch (device globals; no allocation allowed) ----------------
__device__ float g_x  [(size_t)T_TOK * DM];
__device__ float g_u  [(size_t)T_TOK * DM];
__device__ float g_h1 [(size_t)T_TOK * DM];
__device__ float g_ffo[(size_t)T_TOK * DM];
__device__ float g_t3 [(size_t)T_TOK * D_HALF];
__device__ float g_lg [(size_t)T_TOK * NCAT];
// bf16 hi/lo activations
__device__ bf16 g_xh [(size_t)T_TOK * DM],  g_xl [(size_t)T_TOK * DM];
__device__ bf16 g_qh [(size_t)T_TOK * DM],  g_ql [(size_t)T_TOK * DM];
__device__ bf16 g_kTh[(size_t)T_TOK * DM],  g_kTl[(size_t)T_TOK * DM];   // [b][d][n]
__device__ bf16 g_vTh[(size_t)T_TOK * DM],  g_vTl[(size_t)T_TOK * DM];   // [b][d][n]
__device__ bf16 g_Ph [(size_t)D_BATCH*DM*DM], g_Pl [(size_t)D_BATCH*DM*DM];
__device__ bf16 g_M2h[(size_t)D_BATCH*DM*DM], g_M2l[(size_t)D_BATCH*DM*DM]; // transposed
__device__ bf16 g_h1h[(size_t)T_TOK * DM],  g_h1l[(size_t)T_TOK * DM];
__device__ bf16 g_t1h[(size_t)T_TOK * FF],  g_t1l[(size_t)T_TOK * FF];
__device__ bf16 g_h2h[(size_t)T_TOK * DM],  g_h2l[(size_t)T_TOK * DM];
// bf16 hi/lo transposed weights  T[n][k] = W[k][n]
__device__ bf16 g_WqTh[DM*DM], g_WqTl[DM*DM];
__device__ bf16 g_WkTh[DM*DM], g_WkTl[DM*DM];
__device__ bf16 g_WvTh[DM*DM], g_WvTl[DM*DM];
__device__ bf16 g_WuTh[DM*DM], g_WuTl[DM*DM];
__device__ bf16 g_W1Th[(size_t)DM*FF], g_W1Tl[(size_t)DM*FF];
__device__ bf16 g_W2Th[(size_t)DM*FF], g_W2Tl[(size_t)DM*FF];
__device__ bf16 g_W3Th[DM*D_HALF], g_W3Tl[DM*D_HALF];

// ---------------- PTX helpers (all supported on plain compute_103) ----------------
__device__ __forceinline__ uint32_t s2u(const void* p) {
    uint32_t a;
    asm("{ .reg .u64 t; cvta.to.shared.u64 t, %1; cvt.u32.u64 %0, t; }" : "=r"(a) : "l"(p));
    return a;
}
__device__ __forceinline__ void cp_async16(uint32_t dst, const void* src) {
    asm volatile("cp.async.cg.shared.global [%0], [%1], 16;"
                 :: "r"(dst), "l"(__cvta_generic_to_global(src)));
}
#define CP_COMMIT()  asm volatile("cp.async.commit_group;" ::: "memory")
#define CP_WAIT1()   asm volatile("cp.async.wait_group 1;" ::: "memory")

__device__ __forceinline__ void ldsm4(uint32_t* r, uint32_t addr) {
    asm volatile("ldmatrix.sync.aligned.m8n8.x4.shared.b16 {%0,%1,%2,%3}, [%4];"
                 : "=r"(r[0]), "=r"(r[1]), "=r"(r[2]), "=r"(r[3]) : "r"(addr));
}
__device__ __forceinline__ void mma16816(float* c, const uint32_t* a, const uint32_t* b) {
    asm volatile(
        "mma.sync.aligned.m16n8k16.row.col.f32.bf16.bf16.f32 "
        "{%0,%1,%2,%3}, {%4,%5,%6,%7}, {%8,%9}, {%0,%1,%2,%3};"
        : "+f"(c[0]), "+f"(c[1]), "+f"(c[2]), "+f"(c[3])
        : "r"(a[0]), "r"(a[1]), "r"(a[2]), "r"(a[3]), "r"(b[0]), "r"(b[1]));
}

// ---------------- HMMA split-bf16 GEMM ----------------
// D[m,n] = alpha * sum_k (Ah+Al)[m,k]*(Bh+Bl)[n,k] (+bias[n]) (+relu)
// using 3-term split: AhBh + AhBl + AlBh, fp32 accum.
// A: [M,K] K-major (lda, batch sA). B: [N,K] K-major (ldb, batch sB).
// Outputs: fp32 Cf (ldc,sC) and/or bf16 hi/lo Ch/Cl; TRANS_OUT scatters:
//   mg = z*M + m; out[(mg/t_seg)*t_bs + col*t_ld + mg%t_seg]
#define STAGES    3
#define STG_BYTES 65536   // 4 matrices x 128x64 bf16 (16KB each)
#define GEMM_SMEM (STAGES * STG_BYTES)

__device__ __forceinline__ void load_chunk(uint32_t sbase, int s,
        const bf16* Ah, const bf16* Al, const bf16* Bh, const bf16* Bl,
        int lda, int ldb, int m0, int n0, int k0, int tid)
{
    uint32_t base = sbase + s * STG_BYTES;
#pragma unroll
    for (int i = 0; i < 4; ++i) {
        int lin = i * 256 + tid;          // 0..1023
        int row = lin >> 3;               // 0..127
        int u   = lin & 7;                // 16B unit 0..7
        uint32_t soff = row * 128 + (((u ^ (row & 7))) << 4);
        size_t aoff = (size_t)(m0 + row) * lda + k0 + u * 8;
        size_t boff = (size_t)(n0 + row) * ldb + k0 + u * 8;
        cp_async16(base + soff,         Ah + aoff);
        cp_async16(base + 16384 + soff, Al + aoff);
        cp_async16(base + 32768 + soff, Bh + boff);
        cp_async16(base + 49152 + soff, Bl + boff);
    }
}

template<bool TRANS_OUT, bool RELU, bool OUT_F32, bool OUT_BF16>
__global__ void __launch_bounds__(256, 1)
tc_gemm(const bf16* __restrict__ Ah, const bf16* __restrict__ Al, int lda, size_t sA,
        const bf16* __restrict__ Bh, const bf16* __restrict__ Bl, int ldb, size_t sB,
        const float* __restrict__ bias, float alpha,
        float* __restrict__ Cf, bf16* __restrict__ Ch, bf16* __restrict__ Cl,
        int ldc, size_t sC,
        int t_ld, size_t t_bs, int t_seg,
        int M, int K)
{
    extern __shared__ char smem[];
    const int tid  = threadIdx.x;
    const int wid  = tid >> 5;
    const int lane = tid & 31;
    const int wm   = wid >> 1;      // 0..3  (M direction, 32 rows each)
    const int wn   = wid & 1;       // 0..1  (N direction, 64 cols each)
    const int z    = blockIdx.z;
    const int m0   = blockIdx.y * 128;
    const int n0   = blockIdx.x * 128;

    Ah += (size_t)z * sA;  Al += (size_t)z * sA;
    Bh += (size_t)z * sB;  Bl += (size_t)z * sB;

    const uint32_t sb = s2u(smem);

    // per-lane ldmatrix addressing components (swizzle XOR is lane&7 for all)
    const int x7 = lane & 7;
    const int rowA = wm * 32 + ((lane >> 3) & 1) * 8 + x7;  // + mi*16
    const int uA   = lane >> 4;                              // 0/1 -> k half
    const int rowB = wn * 64 + ((lane >> 4) & 1) * 8 + x7;  // + p*16
    const int uB   = (lane >> 3) & 1;

    float acc[2][8][4];
#pragma unroll
    for (int i = 0; i < 2; ++i)
#pragma unroll
        for (int j = 0; j < 8; ++j)
#pragma unroll
            for (int e = 0; e < 4; ++e) acc[i][j][e] = 0.f;

    const int nchunk = K >> 6;

    load_chunk(sb, 0, Ah, Al, Bh, Bl, lda, ldb, m0, n0, 0, tid);
    CP_COMMIT();
    load_chunk(sb, 1, Ah, Al, Bh, Bl, lda, ldb, m0, n0, 64, tid);
    CP_COMMIT();

    for (int c = 0; c < nchunk; ++c) {
        CP_WAIT1();
        __syncthreads();

        if (c + 2 < nchunk)
            load_chunk(sb, (c + 2) % STAGES, Ah, Al, Bh, Bl, lda, ldb, m0, n0, (c + 2) * 64, tid);
        CP_COMMIT();

        const uint32_t stg  = sb + (c % STAGES) * STG_BYTES;
        const uint32_t stAh = stg;
        const uint32_t stAl = stg + 16384;
        const uint32_t stBh = stg + 32768;
        const uint32_t stBl = stg + 49152;

#pragma unroll
        for (int ks = 0; ks < 4; ++ks) {
            uint32_t ah[2][4], al[2][4], bh[4][4], bl[4][4];
            const uint32_t offA = (((2 * ks + uA) ^ x7) << 4);
            const uint32_t offB = (((2 * ks + uB) ^ x7) << 4);
#pragma unroll
            for (int mi = 0; mi < 2; ++mi) {
                uint32_t ra = (uint32_t)(rowA + mi * 16) * 128 + offA;
                ldsm4(ah[mi], stAh + ra);
                ldsm4(al[mi], stAl + ra);
            }
#pragma unroll
            for (int p = 0; p < 4; ++p) {
                uint32_t rb = (uint32_t)(rowB + p * 16) * 128 + offB;
                ldsm4(bh[p], stBh + rb);
                ldsm4(bl[p], stBl + rb);
            }
#pragma unroll
            for (int mi = 0; mi < 2; ++mi) {
#pragma unroll
                for (int p = 0; p < 4; ++p) {
                    mma16816(acc[mi][2 * p + 0], ah[mi], &bh[p][0]);
                    mma16816(acc[mi][2 * p + 0], ah[mi], &bl[p][0]);
                    mma16816(acc[mi][2 * p + 0], al[mi], &bh[p][0]);
                    mma16816(acc[mi][2 * p + 1], ah[mi], &bh[p][2]);
                    mma16816(acc[mi][2 * p + 1], ah[mi], &bl[p][2]);
                    mma16816(acc[mi][2 * p + 1], al[mi], &bh[p][2]);
                }
            }
        }
        __syncthreads();
    }

    // ---- epilogue ----
    const int lr = lane >> 2;         // 0..7
    const int lc = (lane & 3) * 2;    // 0,2,4,6
#pragma unroll
    for (int mi = 0; mi < 2; ++mi) {
#pragma unroll
        for (int h = 0; h < 2; ++h) {
            int row = m0 + wm * 32 + mi * 16 + h * 8 + lr;
            size_t nb = (size_t)z * sC + (size_t)row * ldc;
            size_t tb = 0; int trr = 0;
            if (TRANS_OUT) {
                int mg = z * M + row;
                tb = (size_t)(mg / t_seg) * t_bs;
                trr = mg % t_seg;
            }
#pragma unroll
            for (int nj = 0; nj < 8; ++nj) {
                int col = n0 + wn * 64 + nj * 8 + lc;
                float v0 = acc[mi][nj][h * 2 + 0] * alpha;
                float v1 = acc[mi][nj][h * 2 + 1] * alpha;
                if (bias) { v0 += __ldg(bias + col); v1 += __ldg(bias + col + 1); }
                if (RELU) { v0 = fmaxf(v0, 0.f); v1 = fmaxf(v1, 0.f); }
                if (OUT_F32)
                    *reinterpret_cast<float2*>(Cf + nb + col) = make_float2(v0, v1);
                if (OUT_BF16) {
                    bf16 h0 = __float2bfloat16(v0);
                    bf16 l0 = __float2bfloat16(v0 - __bfloat162float(h0));
                    bf16 h1 = __float2bfloat16(v1);
                    bf16 l1 = __float2bfloat16(v1 - __bfloat162float(h1));
                    if (TRANS_OUT) {
                        size_t a0 = tb + (size_t)col * t_ld + trr;
                        size_t a1 = tb + (size_t)(col + 1) * t_ld + trr;
                        Ch[a0] = h0; Cl[a0] = l0;
                        Ch[a1] = h1; Cl[a1] = l1;
                    } else {
                        uint32_t ph = (uint32_t)__bfloat16_as_ushort(h0) |
                                      ((uint32_t)__bfloat16_as_ushort(h1) << 16);
                        uint32_t pl = (uint32_t)__bfloat16_as_ushort(l0) |
                                      ((uint32_t)__bfloat16_as_ushort(l1) << 16);
                        *reinterpret_cast<uint32_t*>(Ch + nb + col) = ph;
                        *reinterpret_cast<uint32_t*>(Cl + nb + col) = pl;
                    }
                }
            }
        }
    }
}

// ---------------- weight transpose + split:  T[c][r] = split(W[r][c]) ----------------
__global__ void __launch_bounds__(256)
transpose_split_kernel(const float* __restrict__ W, bf16* __restrict__ Th,
                       bf16* __restrict__ Tl, int R, int C)
{
    __shared__ float t[32][33];
    int c0 = blockIdx.x * 32, r0 = blockIdx.y * 32;
    int x = threadIdx.x & 31, y = threadIdx.x >> 5;   // 32 x 8
#pragma unroll
    for (int i = 0; i < 32; i += 8)
        t[y + i][x] = W[(size_t)(r0 + y + i) * C + c0 + x];
    __syncthreads();
#pragma unroll
    for (int i = 0; i < 32; i += 8) {
        float v = t[x][y + i];
        bf16 h = __float2bfloat16(v);
        bf16 l = __float2bfloat16(v - __bfloat162float(h));
        size_t ad = (size_t)(c0 + y + i) * R + r0 + x;
        Th[ad] = h; Tl[ad] = l;
    }
}

// ---------------- embed + positional encoding (fp32 + split) ----------------
__global__ void embed_kernel(const int* __restrict__ idx, const float* __restrict__ emb,
                             float* __restrict__ x, bf16* __restrict__ xh, bf16* __restrict__ xl)
{
    int row = blockIdx.x;
    int pos = row & (N_SEQ - 1);
    int t   = threadIdx.x;
    int id  = idx[row];
    if (id >= VOCAB || id < 0) id = 1;

    int c0 = t * 4;
    int p0 = c0 >> 1, p1 = p0 + 1;
    double inv0 = pow(10000.0, -(double)p0 / 512.0);
    double inv1 = pow(10000.0, -(double)p1 / 512.0);
    float s0, cO0, s1, cO1;
    sincosf((float)((double)pos * inv0), &s0, &cO0);
    sincosf((float)((double)pos * inv1), &s1, &cO1);

    float4 e = *reinterpret_cast<const float4*>(emb + (size_t)id * DM + c0);
    float o[4] = { e.x + s0, e.y + cO0, e.z + s1, e.w + cO1 };
    *reinterpret_cast<float4*>(x + (size_t)row * DM + c0) = make_float4(o[0], o[1], o[2], o[3]);
    size_t ad = (size_t)row * DM + c0;
#pragma unroll
    for (int i = 0; i < 4; ++i) {
        bf16 h = __float2bfloat16(o[i]);
        xh[ad + i] = h;
        xl[ad + i] = __float2bfloat16(o[i] - __bfloat162float(h));
    }
}

// ---------------- residual + layernorm (fp32 in, fp32 + split out) ----------------
__global__ void __launch_bounds__(256)
add_ln_kernel(const float* __restrict__ X, const float* __restrict__ U,
              const float* __restrict__ g, const float* __restrict__ be,
              float* __restrict__ outF, bf16* __restrict__ outH, bf16* __restrict__ outL)
{
    __shared__ float ssum[8], ssq[8];
    __shared__ float smu, srs;
    int row = blockIdx.x;
    int t = threadIdx.x;

    float4 xv = *reinterpret_cast<const float4*>(X + (size_t)row * DM + t * 4);
    float4 uv = *reinterpret_cast<const float4*>(U + (size_t)row * DM + t * 4);
    float v[4] = { xv.x + uv.x, xv.y + uv.y, xv.z + uv.z, xv.w + uv.w };

    float s = v[0] + v[1] + v[2] + v[3];
    float q = v[0]*v[0] + v[1]*v[1] + v[2]*v[2] + v[3]*v[3];
#pragma unroll
    for (int o = 16; o; o >>= 1) {
        s += __shfl_xor_sync(0xFFFFFFFFu, s, o);
        q += __shfl_xor_sync(0xFFFFFFFFu, q, o);
    }
    int warp = t >> 5, lane = t & 31;
    if (lane == 0) { ssum[warp] = s; ssq[warp] = q; }
    __syncthreads();
    if (t == 0) {
        float S = 0.f, Q = 0.f;
#pragma unroll
        for (int i = 0; i < 8; ++i) { S += ssum[i]; Q += ssq[i]; }
        float mu = S * (1.f / DM);
        smu = mu;
        srs = rsqrtf(Q * (1.f / DM) - mu * mu + LN_EPS);
    }
    __syncthreads();
    float mu = smu, rs = srs;

    float4 gv = *reinterpret_cast<const float4*>(g  + t * 4);
    float4 bv = *reinterpret_cast<const float4*>(be + t * 4);
    float gg[4] = { gv.x, gv.y, gv.z, gv.w };
    float bb[4] = { bv.x, bv.y, bv.z, bv.w };
    size_t ad = (size_t)row * DM + t * 4;
    float o4[4];
#pragma unroll
    for (int i = 0; i < 4; ++i) o4[i] = (v[i] - mu) * rs * gg[i] + bb[i];
    if (outF)
        *reinterpret_cast<float4*>(outF + ad) = make_float4(o4[0], o4[1], o4[2], o4[3]);
#pragma unroll
    for (int i = 0; i < 4; ++i) {
        bf16 h = __float2bfloat16(o4[i]);
        outH[ad + i] = h;
        outL[ad + i] = __float2bfloat16(o4[i] - __bfloat162float(h));
    }
}

// ---------------- final: sigmoid(layernorm(logits)) over 75 ----------------
__global__ void __launch_bounds__(256)
final_kernel(const float* __restrict__ lg, const float* __restrict__ g,
             const float* __restrict__ be, float* __restrict__ out)
{
    int row = blockIdx.x * 8 + (threadIdx.x >> 5);
    int lane = threadIdx.x & 31;
    if (row >= T_TOK) return;
    const float* lp = lg + (size_t)row * NCAT;

    float v[3];
    float s = 0.f, q = 0.f;
#pragma unroll
    for (int i = 0; i < 3; ++i) {
        int c = lane + i * 32;
        float x = (c < NCAT) ? lp[c] : 0.f;
        v[i] = x; s += x; q += x * x;
    }
#pragma unroll
    for (int o = 16; o; o >>= 1) {
        s += __shfl_xor_sync(0xFFFFFFFFu, s, o);
        q += __shfl_xor_sync(0xFFFFFFFFu, q, o);
    }
    float mu = s * (1.f / NCAT);
    float rs = rsqrtf(q * (1.f / NCAT) - mu * mu + LN_EPS);

    float* op = out + (size_t)row * NCAT;
#pragma unroll
    for (int i = 0; i < 3; ++i) {
        int c = lane + i * 32;
        if (c < NCAT) {
            float z = (v[i] - mu) * rs * g[c] + be[c];
            op[c] = 1.f / (1.f + expf(-z));
        }
    }
}

// ---------------- fp32 SGEMM (for the tiny N=75 logits GEMM only) ----------------
#define BM 128
#define BN 128
#define BKK 16
__global__ void __launch_bounds__(256)
sgemm_small_n(const float* __restrict__ A, const float* __restrict__ B,
              const float* __restrict__ bias, float* __restrict__ C,
              int M, int N, int K, int lda, int ldb, int ldc)
{
    __shared__ float As[BKK][BM];
    __shared__ float Bs[BKK][BN];
    int m0 = blockIdx.y * BM;
    int n0 = blockIdx.x * BN;
    int tid = threadIdx.x;
    int tx = tid & 15, ty = tid >> 4;

    float acc[8][8];
#pragma unroll
    for (int i = 0; i < 8; ++i)
#pragma unroll
        for (int j = 0; j < 8; ++j) acc[i][j] = 0.f;

    for (int k0 = 0; k0 < K; k0 += BKK) {
#pragma unroll
        for (int it = 0; it < 2; ++it) {
            int idx4 = tid + it * 256;
            int row  = idx4 >> 2;
            int kc   = (idx4 & 3) * 4;
            float4 av = *reinterpret_cast<const float4*>(A + (size_t)(m0 + row) * lda + k0 + kc);
            As[kc + 0][row] = av.x; As[kc + 1][row] = av.y;
            As[kc + 2][row] = av.z; As[kc + 3][row] = av.w;
        }
#pragma unroll
        for (int it = 0; it < 2; ++it) {
            int idx4 = tid + it * 256;
            int row  = idx4 >> 5;
            int nc   = (idx4 & 31) * 4;
            float4 bv = make_float4(0.f, 0.f, 0.f, 0.f);
            int gn = n0 + nc;
            const float* bp = B + (size_t)(k0 + row) * ldb;
            if (gn + 0 < N) bv.x = bp[gn + 0];
            if (gn + 1 < N) bv.y = bp[gn + 1];
            if (gn + 2 < N) bv.z = bp[gn + 2];
            if (gn + 3 < N) bv.w = bp[gn + 3];
            *reinterpret_cast<float4*>(&Bs[row][nc]) = bv;
        }
        __syncthreads();
#pragma unroll
        for (int kk = 0; kk < BKK; ++kk) {
            float a[8], b2[8];
#pragma unroll
            for (int i = 0; i < 8; ++i) a[i] = As[kk][ty * 8 + i];
#pragma unroll
            for (int j = 0; j < 8; ++j) b2[j] = Bs[kk][tx * 8 + j];
#pragma unroll
            for (int i = 0; i < 8; ++i)
#pragma unroll
                for (int j = 0; j < 8; ++j) acc[i][j] += a[i] * b2[j];
        }
        __syncthreads();
    }
#pragma unroll
    for (int i = 0; i < 8; ++i) {
        int gm = m0 + ty * 8 + i;
        float* cp = C + (size_t)gm * ldc;
#pragma unroll
        for (int j = 0; j < 8; ++j) {
            int gn = n0 + tx * 8 + j;
            if (gn < N) cp[gn] = acc[i][j] + bias[gn];
        }
    }
}

// ---------------- host launcher ----------------
static bool g_attr_done = false;

extern "C" void kernel_launch(void* const* d_in, const int* in_sizes, int n_in,
                              void* d_out, int out_size)
{
    const int*   idx = (const int*)  d_in[0];
    const float* emb = (const float*)d_in[1];
    const float* Wq  = (const float*)d_in[2];
    const float* bq  = (const float*)d_in[3];
    const float* Wk  = (const float*)d_in[4];
    const float* bk  = (const float*)d_in[5];
    const float* Wv  = (const float*)d_in[6];
    const float* bv  = (const float*)d_in[7];
    const float* Wu  = (const float*)d_in[8];
    const float* bu  = (const float*)d_in[9];
    const float* g1  = (const float*)d_in[10];
    const float* be1 = (const float*)d_in[11];
    const float* W1  = (const float*)d_in[12];
    const float* b1  = (const float*)d_in[13];
    const float* W2  = (const float*)d_in[14];
    const float* b2  = (const float*)d_in[15];
    const float* g2  = (const float*)d_in[16];
    const float* be2 = (const float*)d_in[17];
    const float* W3  = (const float*)d_in[18];
    const float* b3  = (const float*)d_in[19];
    const float* W4  = (const float*)d_in[20];
    const float* b4  = (const float*)d_in[21];
    const float* g3  = (const float*)d_in[22];
    const float* be3 = (const float*)d_in[23];
    float* out = (float*)d_out;

    if (!g_attr_done) {
        cudaFuncSetAttribute(tc_gemm<false,false,false,true>, cudaFuncAttributeMaxDynamicSharedMemorySize, GEMM_SMEM);
        cudaFuncSetAttribute(tc_gemm<true ,false,false,true>, cudaFuncAttributeMaxDynamicSharedMemorySize, GEMM_SMEM);
        cudaFuncSetAttribute(tc_gemm<false,false,true ,false>, cudaFuncAttributeMaxDynamicSharedMemorySize, GEMM_SMEM);
        cudaFuncSetAttribute(tc_gemm<false,true ,false,true>, cudaFuncAttributeMaxDynamicSharedMemorySize, GEMM_SMEM);
        cudaFuncSetAttribute(tc_gemm<false,true ,true ,false>, cudaFuncAttributeMaxDynamicSharedMemorySize, GEMM_SMEM);
        g_attr_done = true;
    }

    float *x, *u, *h1, *ffo, *t3, *lg;
    bf16 *xh, *xl, *qh, *ql, *kTh, *kTl, *vTh, *vTl, *Ph, *Pl, *M2h, *M2l;
    bf16 *h1h, *h1l, *t1h, *t1l, *h2h, *h2l;
    bf16 *WqTh, *WqTl, *WkTh, *WkTl, *WvTh, *WvTl, *WuTh, *WuTl;
    bf16 *W1Th, *W1Tl, *W2Th, *W2Tl, *W3Th, *W3Tl;
    cudaGetSymbolAddress((void**)&x,   g_x);
    cudaGetSymbolAddress((void**)&u,   g_u);
    cudaGetSymbolAddress((void**)&h1,  g_h1);
    cudaGetSymbolAddress((void**)&ffo, g_ffo);
    cudaGetSymbolAddress((void**)&t3,  g_t3);
    cudaGetSymbolAddress((void**)&lg,  g_lg);
    cudaGetSymbolAddress((void**)&xh,  g_xh);  cudaGetSymbolAddress((void**)&xl,  g_xl);
    cudaGetSymbolAddress((void**)&qh,  g_qh);  cudaGetSymbolAddress((void**)&ql,  g_ql);
    cudaGetSymbolAddress((void**)&kTh, g_kTh); cudaGetSymbolAddress((void**)&kTl, g_kTl);
    cudaGetSymbolAddress((void**)&vTh, g_vTh); cudaGetSymbolAddress((void**)&vTl, g_vTl);
    cudaGetSymbolAddress((void**)&Ph,  g_Ph);  cudaGetSymbolAddress((void**)&Pl,  g_Pl);
    cudaGetSymbolAddress((void**)&M2h, g_M2h); cudaGetSymbolAddress((void**)&M2l, g_M2l);
    cudaGetSymbolAddress((void**)&h1h, g_h1h); cudaGetSymbolAddress((void**)&h1l, g_h1l);
    cudaGetSymbolAddress((void**)&t1h, g_t1h); cudaGetSymbolAddress((void**)&t1l, g_t1l);
    cudaGetSymbolAddress((void**)&h2h, g_h2h); cudaGetSymbolAddress((void**)&h2l, g_h2l);
    cudaGetSymbolAddress((void**)&WqTh, g_WqTh); cudaGetSymbolAddress((void**)&WqTl, g_WqTl);
    cudaGetSymbolAddress((void**)&WkTh, g_WkTh); cudaGetSymbolAddress((void**)&WkTl, g_WkTl);
    cudaGetSymbolAddress((void**)&WvTh, g_WvTh); cudaGetSymbolAddress((void**)&WvTl, g_WvTl);
    cudaGetSymbolAddress((void**)&WuTh, g_WuTh); cudaGetSymbolAddress((void**)&WuTl, g_WuTl);
    cudaGetSymbolAddress((void**)&W1Th, g_W1Th); cudaGetSymbolAddress((void**)&W1Tl, g_W1Tl);
    cudaGetSymbolAddress((void**)&W2Th, g_W2Th); cudaGetSymbolAddress((void**)&W2Tl, g_W2Tl);
    cudaGetSymbolAddress((void**)&W3Th, g_W3Th); cudaGetSymbolAddress((void**)&W3Tl, g_W3Tl);

    // ---- weight prep: transpose + split ----
    dim3 tb(256);
    transpose_split_kernel<<<dim3(DM/32, DM/32), tb>>>(Wq, WqTh, WqTl, DM, DM);
    transpose_split_kernel<<<dim3(DM/32, DM/32), tb>>>(Wk, WkTh, WkTl, DM, DM);
    transpose_split_kernel<<<dim3(DM/32, DM/32), tb>>>(Wv, WvTh, WvTl, DM, DM);
    transpose_split_kernel<<<dim3(DM/32, DM/32), tb>>>(Wu, WuTh, WuTl, DM, DM);
    transpose_split_kernel<<<dim3(FF/32, DM/32), tb>>>(W1, W1Th, W1Tl, DM, FF);
    transpose_split_kernel<<<dim3(DM/32, FF/32), tb>>>(W2, W2Th, W2Tl, FF, DM);
    transpose_split_kernel<<<dim3(D_HALF/32, DM/32), tb>>>(W3, W3Th, W3Tl, DM, D_HALF);

    // ---- 1. x = emb[idx] + posenc ----
    embed_kernel<<<T_TOK, 256>>>(idx, emb, x, xh, xl);

    // ---- 2-4. Q/K/V projections ----
    tc_gemm<false,false,false,true><<<dim3(8,128,1), 256, GEMM_SMEM>>>(
        xh, xl, DM, 0, WqTh, WqTl, DM, 0, bq, 1.f,
        nullptr, qh, ql, DM, 0, 0, 0, 1, T_TOK, DM);
    tc_gemm<true,false,false,true><<<dim3(8,128,1), 256, GEMM_SMEM>>>(
        xh, xl, DM, 0, WkTh, WkTl, DM, 0, bk, 1.f,
        nullptr, kTh, kTl, 0, 0, N_SEQ, (size_t)DM*N_SEQ, N_SEQ, T_TOK, DM);
    tc_gemm<true,false,false,true><<<dim3(8,128,1), 256, GEMM_SMEM>>>(
        xh, xl, DM, 0, WvTh, WvTl, DM, 0, bv, 1.f,
        nullptr, vTh, vTl, 0, 0, N_SEQ, (size_t)DM*N_SEQ, N_SEQ, T_TOK, DM);

    // ---- 5. P[b] = K^T V ----
    tc_gemm<false,false,false,true><<<dim3(8,8,D_BATCH), 256, GEMM_SMEM>>>(
        kTh, kTl, N_SEQ, (size_t)DM*N_SEQ, vTh, vTl, N_SEQ, (size_t)DM*N_SEQ,
        nullptr, 1.f, nullptr, Ph, Pl, DM, (size_t)DM*DM, 0, 0, 1, DM, N_SEQ);

    // ---- 6. M2^T[b] = (P @ Wu)^T / 8 ----
    tc_gemm<true,false,false,true><<<dim3(8,8,D_BATCH), 256, GEMM_SMEM>>>(
        Ph, Pl, DM, (size_t)DM*DM, WuTh, WuTl, DM, 0,
        nullptr, 0.125f, nullptr, M2h, M2l, 0, 0, DM, (size_t)DM*DM, DM, DM, DM);

    // ---- 7. u = Q @ M2 + bu (fp32 out) ----
    tc_gemm<false,false,true,false><<<dim3(8,16,D_BATCH), 256, GEMM_SMEM>>>(
        qh, ql, DM, (size_t)N_SEQ*DM, M2h, M2l, DM, (size_t)DM*DM,
        bu, 1.f, u, nullptr, nullptr, DM, (size_t)N_SEQ*DM, 0, 0, 1, N_SEQ, DM);

    // ---- 8. h1 = LN(x + u) ----
    add_ln_kernel<<<T_TOK, 256>>>(x, u, g1, be1, h1, h1h, h1l);

    // ---- 9. t1 = relu(h1 @ W1 + b1) ----
    tc_gemm<false,true,false,true><<<dim3(32,128,1), 256, GEMM_SMEM>>>(
        h1h, h1l, DM, 0, W1Th, W1Tl, DM, 0, b1, 1.f,
        nullptr, t1h, t1l, FF, 0, 0, 0, 1, T_TOK, DM);

    // ---- 10. ffo = t1 @ W2 + b2 (fp32 out) ----
    tc_gemm<false,false,true,false><<<dim3(8,128,1), 256, GEMM_SMEM>>>(
        t1h, t1l, FF, 0, W2Th, W2Tl, FF, 0, b2, 1.f,
        ffo, nullptr, nullptr, DM, 0, 0, 0, 1, T_TOK, FF);

    // ---- 11. h2 = LN(h1 + ffo) ----
    add_ln_kernel<<<T_TOK, 256>>>(h1, ffo, g2, be2, nullptr, h2h, h2l);

    // ---- 12. t3 = relu(h2 @ W3 + b3) (fp32 out) ----
    tc_gemm<false,true,true,false><<<dim3(4,128,1), 256, GEMM_SMEM>>>(
        h2h, h2l, DM, 0, W3Th, W3Tl, DM, 0, b3, 1.f,
        t3, nullptr, nullptr, D_HALF, 0, 0, 0, 1, T_TOK, DM);

    // ---- 13. logits = t3 @ W4 + b4 (fp32 SGEMM, N=75) ----
    sgemm_small_n<<<dim3(1, T_TOK/BM, 1), 256>>>(t3, W4, b4, lg,
                                                 T_TOK, NCAT, D_HALF, D_HALF, NCAT, NCAT);

    // ---- 14. out = sigmoid(LN(logits)) ----
    final_kernel<<<T_TOK/8, 256>>>(lg, g3, be3, out);
}

// round 6
// speedup vs baseline: 2.8350x; 1.0015x over previous
#include <cuda_runtime.h>
#include <cuda_bf16.h>
#include <cstdint>
#include <math.h>

// ---------------- problem constants ----------------
#define D_BATCH 8
#define N_SEQ   2048
#define T_TOK   16384
#define DM      1024
#define FF      4096
#define VOCAB   32000
#define NCAT    75
#define D_HALF  512
#define LN_EPS  1e-5f

typedef __nv_bfloat16 bf16;

// ---------------- scratch (device globals; no allocation allowed) ----------------
__device__ float g_x  [(size_t)T_TOK * DM];
__device__ float g_u  [(size_t)T_TOK * DM];
__device__ float g_h1 [(size_t)T_TOK * DM];
__device__ float g_ffo[(size_t)T_TOK * DM];
__device__ float g_t3 [(size_t)T_TOK * D_HALF];
__device__ float g_lg [(size_t)T_TOK * NCAT];
// bf16 hi/lo activations
__device__ bf16 g_xh [(size_t)T_TOK * DM],  g_xl [(size_t)T_TOK * DM];
__device__ bf16 g_qh [(size_t)T_TOK * DM],  g_ql [(size_t)T_TOK * DM];
__device__ bf16 g_kTh[(size_t)T_TOK * DM],  g_kTl[(size_t)T_TOK * DM];   // [b][d][n]
__device__ bf16 g_vTh[(size_t)T_TOK * DM],  g_vTl[(size_t)T_TOK * DM];   // [b][d][n]
__device__ bf16 g_Ph [(size_t)D_BATCH*DM*DM], g_Pl [(size_t)D_BATCH*DM*DM];
__device__ bf16 g_M2h[(size_t)D_BATCH*DM*DM], g_M2l[(size_t)D_BATCH*DM*DM]; // transposed
__device__ bf16 g_h1h[(size_t)T_TOK * DM],  g_h1l[(size_t)T_TOK * DM];
__device__ bf16 g_t1h[(size_t)T_TOK * FF],  g_t1l[(size_t)T_TOK * FF];
__device__ bf16 g_h2h[(size_t)T_TOK * DM],  g_h2l[(size_t)T_TOK * DM];
// bf16 hi/lo transposed weights  T[n][k] = W[k][n]
__device__ bf16 g_WqTh[DM*DM], g_WqTl[DM*DM];
__device__ bf16 g_WkTh[DM*DM], g_WkTl[DM*DM];
__device__ bf16 g_WvTh[DM*DM], g_WvTl[DM*DM];
__device__ bf16 g_WuTh[DM*DM], g_WuTl[DM*DM];
__device__ bf16 g_W1Th[(size_t)DM*FF], g_W1Tl[(size_t)DM*FF];
__device__ bf16 g_W2Th[(size_t)DM*FF], g_W2Tl[(size_t)DM*FF];
__device__ bf16 g_W3Th[DM*D_HALF], g_W3Tl[DM*D_HALF];

// ---------------- PTX helpers (all supported on plain compute_103) ----------------
__device__ __forceinline__ uint32_t s2u(const void* p) {
    uint32_t a;
    asm("{ .reg .u64 t; cvta.to.shared.u64 t, %1; cvt.u32.u64 %0, t; }" : "=r"(a) : "l"(p));
    return a;
}
__device__ __forceinline__ void cp_async16(uint32_t dst, const void* src) {
    asm volatile("cp.async.cg.shared.global [%0], [%1], 16;"
                 :: "r"(dst), "l"(__cvta_generic_to_global(src)));
}
#define CP_COMMIT()  asm volatile("cp.async.commit_group;" ::: "memory")
#define CP_WAIT1()   asm volatile("cp.async.wait_group 1;" ::: "memory")

__device__ __forceinline__ void ldsm4(uint32_t* r, uint32_t addr) {
    asm volatile("ldmatrix.sync.aligned.m8n8.x4.shared.b16 {%0,%1,%2,%3}, [%4];"
                 : "=r"(r[0]), "=r"(r[1]), "=r"(r[2]), "=r"(r[3]) : "r"(addr));
}
__device__ __forceinline__ void mma16816(float* c, const uint32_t* a, const uint32_t* b) {
    asm volatile(
        "mma.sync.aligned.m16n8k16.row.col.f32.bf16.bf16.f32 "
        "{%0,%1,%2,%3}, {%4,%5,%6,%7}, {%8,%9}, {%0,%1,%2,%3};"
        : "+f"(c[0]), "+f"(c[1]), "+f"(c[2]), "+f"(c[3])
        : "r"(a[0]), "r"(a[1]), "r"(a[2]), "r"(a[3]), "r"(b[0]), "r"(b[1]));
}

// ---------------- HMMA split-bf16 GEMM ----------------
// D[m,n] = alpha * sum_k (Ah+Al)[m,k]*(Bh+Bl)[n,k] (+bias[n]) (+relu)
// 3-term split: AhBh + AhBl + AlBh, fp32 accum, terms interleaved across
// all 16 accumulator tiles so consecutive MMAs are independent.
#define STAGES    3
#define STG_BYTES 65536   // 4 matrices x 128x64 bf16 (16KB each)
#define GEMM_SMEM (STAGES * STG_BYTES)

__device__ __forceinline__ void load_chunk(uint32_t sbase, int s,
        const bf16* Ah, const bf16* Al, const bf16* Bh, const bf16* Bl,
        int lda, int ldb, int m0, int n0, int k0, int tid)
{
    uint32_t base = sbase + s * STG_BYTES;
#pragma unroll
    for (int i = 0; i < 4; ++i) {
        int lin = i * 256 + tid;          // 0..1023
        int row = lin >> 3;               // 0..127
        int u   = lin & 7;                // 16B unit 0..7
        uint32_t soff = row * 128 + (((u ^ (row & 7))) << 4);
        size_t aoff = (size_t)(m0 + row) * lda + k0 + u * 8;
        size_t boff = (size_t)(n0 + row) * ldb + k0 + u * 8;
        cp_async16(base + soff,         Ah + aoff);
        cp_async16(base + 16384 + soff, Al + aoff);
        cp_async16(base + 32768 + soff, Bh + boff);
        cp_async16(base + 49152 + soff, Bl + boff);
    }
}

template<bool TRANS_OUT, bool RELU, bool OUT_F32, bool OUT_BF16>
__global__ void __launch_bounds__(256, 1)
tc_gemm(const bf16* __restrict__ Ah, const bf16* __restrict__ Al, int lda, size_t sA,
        const bf16* __restrict__ Bh, const bf16* __restrict__ Bl, int ldb, size_t sB,
        const float* __restrict__ bias, float alpha,
        float* __restrict__ Cf, bf16* __restrict__ Ch, bf16* __restrict__ Cl,
        int ldc, size_t sC,
        int t_ld, size_t t_bs, int t_seg,
        int M, int K)
{
    extern __shared__ char smem[];
    const int tid  = threadIdx.x;
    const int wid  = tid >> 5;
    const int lane = tid & 31;
    const int wm   = wid >> 1;      // 0..3  (M direction, 32 rows each)
    const int wn   = wid & 1;       // 0..1  (N direction, 64 cols each)
    const int z    = blockIdx.z;
    const int m0   = blockIdx.y * 128;
    const int n0   = blockIdx.x * 128;

    Ah += (size_t)z * sA;  Al += (size_t)z * sA;
    Bh += (size_t)z * sB;  Bl += (size_t)z * sB;

    const uint32_t sb = s2u(smem);

    const int x7 = lane & 7;
    const int rowA = wm * 32 + ((lane >> 3) & 1) * 8 + x7;  // + mi*16
    const int uA   = lane >> 4;
    const int rowB = wn * 64 + ((lane >> 4) & 1) * 8 + x7;  // + p*16
    const int uB   = (lane >> 3) & 1;

    float acc[2][8][4];
#pragma unroll
    for (int i = 0; i < 2; ++i)
#pragma unroll
        for (int j = 0; j < 8; ++j)
#pragma unroll
            for (int e = 0; e < 4; ++e) acc[i][j][e] = 0.f;

    const int nchunk = K >> 6;

    load_chunk(sb, 0, Ah, Al, Bh, Bl, lda, ldb, m0, n0, 0, tid);
    CP_COMMIT();
    load_chunk(sb, 1, Ah, Al, Bh, Bl, lda, ldb, m0, n0, 64, tid);
    CP_COMMIT();

    for (int c = 0; c < nchunk; ++c) {
        CP_WAIT1();
        __syncthreads();

        if (c + 2 < nchunk)
            load_chunk(sb, (c + 2) % STAGES, Ah, Al, Bh, Bl, lda, ldb, m0, n0, (c + 2) * 64, tid);
        CP_COMMIT();

        const uint32_t stg  = sb + (c % STAGES) * STG_BYTES;
        const uint32_t stAh = stg;
        const uint32_t stAl = stg + 16384;
        const uint32_t stBh = stg + 32768;
        const uint32_t stBl = stg + 49152;

#pragma unroll
        for (int ks = 0; ks < 4; ++ks) {
            uint32_t ah[2][4], al[2][4], bh[4][4], bl[4][4];
            const uint32_t offA = (((2 * ks + uA) ^ x7) << 4);
            const uint32_t offB = (((2 * ks + uB) ^ x7) << 4);
#pragma unroll
            for (int mi = 0; mi < 2; ++mi) {
                uint32_t ra = (uint32_t)(rowA + mi * 16) * 128 + offA;
                ldsm4(ah[mi], stAh + ra);
                ldsm4(al[mi], stAl + ra);
            }
#pragma unroll
            for (int p = 0; p < 4; ++p) {
                uint32_t rb = (uint32_t)(rowB + p * 16) * 128 + offB;
                ldsm4(bh[p], stBh + rb);
                ldsm4(bl[p], stBl + rb);
            }
            // term 1: Ah*Bh — 16 independent MMAs
#pragma unroll
            for (int mi = 0; mi < 2; ++mi)
#pragma unroll
                for (int p = 0; p < 4; ++p) {
                    mma16816(acc[mi][2 * p + 0], ah[mi], &bh[p][0]);
                    mma16816(acc[mi][2 * p + 1], ah[mi], &bh[p][2]);
                }
            // term 2: Ah*Bl — 16 independent MMAs (each acc last touched 16 MMAs ago)
#pragma unroll
            for (int mi = 0; mi < 2; ++mi)
#pragma unroll
                for (int p = 0; p < 4; ++p) {
                    mma16816(acc[mi][2 * p + 0], ah[mi], &bl[p][0]);
                    mma16816(acc[mi][2 * p + 1], ah[mi], &bl[p][2]);
                }
            // term 3: Al*Bh
#pragma unroll
            for (int mi = 0; mi < 2; ++mi)
#pragma unroll
                for (int p = 0; p < 4; ++p) {
                    mma16816(acc[mi][2 * p + 0], al[mi], &bh[p][0]);
                    mma16816(acc[mi][2 * p + 1], al[mi], &bh[p][2]);
                }
        }
        __syncthreads();
    }

    // ---- epilogue ----
    const int lr = lane >> 2;         // 0..7
    const int lc = (lane & 3) * 2;    // 0,2,4,6
#pragma unroll
    for (int mi = 0; mi < 2; ++mi) {
#pragma unroll
        for (int h = 0; h < 2; ++h) {
            int row = m0 + wm * 32 + mi * 16 + h * 8 + lr;
            size_t nb = (size_t)z * sC + (size_t)row * ldc;
            size_t tb = 0; int trr = 0;
            if (TRANS_OUT) {
                int mg = z * M + row;
                tb = (size_t)(mg / t_seg) * t_bs;
                trr = mg % t_seg;
            }
#pragma unroll
            for (int nj = 0; nj < 8; ++nj) {
                int col = n0 + wn * 64 + nj * 8 + lc;
                float v0 = acc[mi][nj][h * 2 + 0] * alpha;
                float v1 = acc[mi][nj][h * 2 + 1] * alpha;
                if (bias) { v0 += __ldg(bias + col); v1 += __ldg(bias + col + 1); }
                if (RELU) { v0 = fmaxf(v0, 0.f); v1 = fmaxf(v1, 0.f); }
                if (OUT_F32)
                    *reinterpret_cast<float2*>(Cf + nb + col) = make_float2(v0, v1);
                if (OUT_BF16) {
                    bf16 h0 = __float2bfloat16(v0);
                    bf16 l0 = __float2bfloat16(v0 - __bfloat162float(h0));
                    bf16 h1 = __float2bfloat16(v1);
                    bf16 l1 = __float2bfloat16(v1 - __bfloat162float(h1));
                    if (TRANS_OUT) {
                        size_t a0 = tb + (size_t)col * t_ld + trr;
                        size_t a1 = tb + (size_t)(col + 1) * t_ld + trr;
                        Ch[a0] = h0; Cl[a0] = l0;
                        Ch[a1] = h1; Cl[a1] = l1;
                    } else {
                        uint32_t ph = (uint32_t)__bfloat16_as_ushort(h0) |
                                      ((uint32_t)__bfloat16_as_ushort(h1) << 16);
                        uint32_t pl = (uint32_t)__bfloat16_as_ushort(l0) |
                                      ((uint32_t)__bfloat16_as_ushort(l1) << 16);
                        *reinterpret_cast<uint32_t*>(Ch + nb + col) = ph;
                        *reinterpret_cast<uint32_t*>(Cl + nb + col) = pl;
                    }
                }
            }
        }
    }
}

// ---------------- weight transpose + split:  T[c][r] = split(W[r][c]) ----------------
__global__ void __launch_bounds__(256)
transpose_split_kernel(const float* __restrict__ W, bf16* __restrict__ Th,
                       bf16* __restrict__ Tl, int R, int C)
{
    __shared__ float t[32][33];
    int c0 = blockIdx.x * 32, r0 = blockIdx.y * 32;
    int x = threadIdx.x & 31, y = threadIdx.x >> 5;   // 32 x 8
#pragma unroll
    for (int i = 0; i < 32; i += 8)
        t[y + i][x] = W[(size_t)(r0 + y + i) * C + c0 + x];
    __syncthreads();
#pragma unroll
    for (int i = 0; i < 32; i += 8) {
        float v = t[x][y + i];
        bf16 h = __float2bfloat16(v);
        bf16 l = __float2bfloat16(v - __bfloat162float(h));
        size_t ad = (size_t)(c0 + y + i) * R + r0 + x;
        Th[ad] = h; Tl[ad] = l;
    }
}

// ---------------- embed + positional encoding (fp32 + split) ----------------
__global__ void embed_kernel(const int* __restrict__ idx, const float* __restrict__ emb,
                             float* __restrict__ x, bf16* __restrict__ xh, bf16* __restrict__ xl)
{
    int row = blockIdx.x;
    int pos = row & (N_SEQ - 1);
    int t   = threadIdx.x;
    int id  = idx[row];
    if (id >= VOCAB || id < 0) id = 1;

    int c0 = t * 4;
    int p0 = c0 >> 1, p1 = p0 + 1;
    double inv0 = pow(10000.0, -(double)p0 / 512.0);
    double inv1 = pow(10000.0, -(double)p1 / 512.0);
    float s0, cO0, s1, cO1;
    sincosf((float)((double)pos * inv0), &s0, &cO0);
    sincosf((float)((double)pos * inv1), &s1, &cO1);

    float4 e = *reinterpret_cast<const float4*>(emb + (size_t)id * DM + c0);
    float o[4] = { e.x + s0, e.y + cO0, e.z + s1, e.w + cO1 };
    *reinterpret_cast<float4*>(x + (size_t)row * DM + c0) = make_float4(o[0], o[1], o[2], o[3]);
    size_t ad = (size_t)row * DM + c0;
#pragma unroll
    for (int i = 0; i < 4; ++i) {
        bf16 h = __float2bfloat16(o[i]);
        xh[ad + i] = h;
        xl[ad + i] = __float2bfloat16(o[i] - __bfloat162float(h));
    }
}

// ---------------- residual + layernorm (fp32 in, fp32 + split out) ----------------
__global__ void __launch_bounds__(256)
add_ln_kernel(const float* __restrict__ X, const float* __restrict__ U,
              const float* __restrict__ g, const float* __restrict__ be,
              float* __restrict__ outF, bf16* __restrict__ outH, bf16* __restrict__ outL)
{
    __shared__ float ssum[8], ssq[8];
    __shared__ float smu, srs;
    int row = blockIdx.x;
    int t = threadIdx.x;

    float4 xv = *reinterpret_cast<const float4*>(X + (size_t)row * DM + t * 4);
    float4 uv = *reinterpret_cast<const float4*>(U + (size_t)row * DM + t * 4);
    float v[4] = { xv.x + uv.x, xv.y + uv.y, xv.z + uv.z, xv.w + uv.w };

    float s = v[0] + v[1] + v[2] + v[3];
    float q = v[0]*v[0] + v[1]*v[1] + v[2]*v[2] + v[3]*v[3];
#pragma unroll
    for (int o = 16; o; o >>= 1) {
        s += __shfl_xor_sync(0xFFFFFFFFu, s, o);
        q += __shfl_xor_sync(0xFFFFFFFFu, q, o);
    }
    int warp = t >> 5, lane = t & 31;
    if (lane == 0) { ssum[warp] = s; ssq[warp] = q; }
    __syncthreads();
    if (t == 0) {
        float S = 0.f, Q = 0.f;
#pragma unroll
        for (int i = 0; i < 8; ++i) { S += ssum[i]; Q += ssq[i]; }
        float mu = S * (1.f / DM);
        smu = mu;
        srs = rsqrtf(Q * (1.f / DM) - mu * mu + LN_EPS);
    }
    __syncthreads();
    float mu = smu, rs = srs;

    float4 gv = *reinterpret_cast<const float4*>(g  + t * 4);
    float4 bv = *reinterpret_cast<const float4*>(be + t * 4);
    float gg[4] = { gv.x, gv.y, gv.z, gv.w };
    float bb[4] = { bv.x, bv.y, bv.z, bv.w };
    size_t ad = (size_t)row * DM + t * 4;
    float o4[4];
#pragma unroll
    for (int i = 0; i < 4; ++i) o4[i] = (v[i] - mu) * rs * gg[i] + bb[i];
    if (outF)
        *reinterpret_cast<float4*>(outF + ad) = make_float4(o4[0], o4[1], o4[2], o4[3]);
#pragma unroll
    for (int i = 0; i < 4; ++i) {
        bf16 h = __float2bfloat16(o4[i]);
        outH[ad + i] = h;
        outL[ad + i] = __float2bfloat16(o4[i] - __bfloat162float(h));
    }
}

// ---------------- final: sigmoid(layernorm(logits)) over 75 ----------------
__global__ void __launch_bounds__(256)
final_kernel(const float* __restrict__ lg, const float* __restrict__ g,
             const float* __restrict__ be, float* __restrict__ out)
{
    int row = blockIdx.x * 8 + (threadIdx.x >> 5);
    int lane = threadIdx.x & 31;
    if (row >= T_TOK) return;
    const float* lp = lg + (size_t)row * NCAT;

    float v[3];
    float s = 0.f, q = 0.f;
#pragma unroll
    for (int i = 0; i < 3; ++i) {
        int c = lane + i * 32;
        float x = (c < NCAT) ? lp[c] : 0.f;
        v[i] = x; s += x; q += x * x;
    }
#pragma unroll
    for (int o = 16; o; o >>= 1) {
        s += __shfl_xor_sync(0xFFFFFFFFu, s, o);
        q += __shfl_xor_sync(0xFFFFFFFFu, q, o);
    }
    float mu = s * (1.f / NCAT);
    float rs = rsqrtf(q * (1.f / NCAT) - mu * mu + LN_EPS);

    float* op = out + (size_t)row * NCAT;
#pragma unroll
    for (int i = 0; i < 3; ++i) {
        int c = lane + i * 32;
        if (c < NCAT) {
            float z = (v[i] - mu) * rs * g[c] + be[c];
            op[c] = 1.f / (1.f + expf(-z));
        }
    }
}

// ---------------- fp32 SGEMM (for the tiny N=75 logits GEMM only) ----------------
#define BM 128
#define BN 128
#define BKK 16
__global__ void __launch_bounds__(256)
sgemm_small_n(const float* __restrict__ A, const float* __restrict__ B,
              const float* __restrict__ bias, float* __restrict__ C,
              int M, int N, int K, int lda, int ldb, int ldc)
{
    __shared__ float As[BKK][BM];
    __shared__ float Bs[BKK][BN];
    int m0 = blockIdx.y * BM;
    int n0 = blockIdx.x * BN;
    int tid = threadIdx.x;
    int tx = tid & 15, ty = tid >> 4;

    float acc[8][8];
#pragma unroll
    for (int i = 0; i < 8; ++i)
#pragma unroll
        for (int j = 0; j < 8; ++j) acc[i][j] = 0.f;

    for (int k0 = 0; k0 < K; k0 += BKK) {
#pragma unroll
        for (int it = 0; it < 2; ++it) {
            int idx4 = tid + it * 256;
            int row  = idx4 >> 2;
            int kc   = (idx4 & 3) * 4;
            float4 av = *reinterpret_cast<const float4*>(A + (size_t)(m0 + row) * lda + k0 + kc);
            As[kc + 0][row] = av.x; As[kc + 1][row] = av.y;
            As[kc + 2][row] = av.z; As[kc + 3][row] = av.w;
        }
#pragma unroll
        for (int it = 0; it < 2; ++it) {
            int idx4 = tid + it * 256;
            int row  = idx4 >> 5;
            int nc   = (idx4 & 31) * 4;
            float4 bv = make_float4(0.f, 0.f, 0.f, 0.f);
            int gn = n0 + nc;
            const float* bp = B + (size_t)(k0 + row) * ldb;
            if (gn + 0 < N) bv.x = bp[gn + 0];
            if (gn + 1 < N) bv.y = bp[gn + 1];
            if (gn + 2 < N) bv.z = bp[gn + 2];
            if (gn + 3 < N) bv.w = bp[gn + 3];
            *reinterpret_cast<float4*>(&Bs[row][nc]) = bv;
        }
        __syncthreads();
#pragma unroll
        for (int kk = 0; kk < BKK; ++kk) {
            float a[8], b2[8];
#pragma unroll
            for (int i = 0; i < 8; ++i) a[i] = As[kk][ty * 8 + i];
#pragma unroll
            for (int j = 0; j < 8; ++j) b2[j] = Bs[kk][tx * 8 + j];
#pragma unroll
            for (int i = 0; i < 8; ++i)
#pragma unroll
                for (int j = 0; j < 8; ++j) acc[i][j] += a[i] * b2[j];
        }
        __syncthreads();
    }
#pragma unroll
    for (int i = 0; i < 8; ++i) {
        int gm = m0 + ty * 8 + i;
        float* cp = C + (size_t)gm * ldc;
#pragma unroll
        for (int j = 0; j < 8; ++j) {
            int gn = n0 + tx * 8 + j;
            if (gn < N) cp[gn] = acc[i][j] + bias[gn];
        }
    }
}

// ---------------- host launcher ----------------
static bool g_attr_done = false;

extern "C" void kernel_launch(void* const* d_in, const int* in_sizes, int n_in,
                              void* d_out, int out_size)
{
    const int*   idx = (const int*)  d_in[0];
    const float* emb = (const float*)d_in[1];
    const float* Wq  = (const float*)d_in[2];
    const float* bq  = (const float*)d_in[3];
    const float* Wk  = (const float*)d_in[4];
    const float* bk  = (const float*)d_in[5];
    const float* Wv  = (const float*)d_in[6];
    const float* bv  = (const float*)d_in[7];
    const float* Wu  = (const float*)d_in[8];
    const float* bu  = (const float*)d_in[9];
    const float* g1  = (const float*)d_in[10];
    const float* be1 = (const float*)d_in[11];
    const float* W1  = (const float*)d_in[12];
    const float* b1  = (const float*)d_in[13];
    const float* W2  = (const float*)d_in[14];
    const float* b2  = (const float*)d_in[15];
    const float* g2  = (const float*)d_in[16];
    const float* be2 = (const float*)d_in[17];
    const float* W3  = (const float*)d_in[18];
    const float* b3  = (const float*)d_in[19];
    const float* W4  = (const float*)d_in[20];
    const float* b4  = (const float*)d_in[21];
    const float* g3  = (const float*)d_in[22];
    const float* be3 = (const float*)d_in[23];
    float* out = (float*)d_out;

    if (!g_attr_done) {
        cudaFuncSetAttribute(tc_gemm<false,false,false,true>, cudaFuncAttributeMaxDynamicSharedMemorySize, GEMM_SMEM);
        cudaFuncSetAttribute(tc_gemm<true ,false,false,true>, cudaFuncAttributeMaxDynamicSharedMemorySize, GEMM_SMEM);
        cudaFuncSetAttribute(tc_gemm<false,false,true ,false>, cudaFuncAttributeMaxDynamicSharedMemorySize, GEMM_SMEM);
        cudaFuncSetAttribute(tc_gemm<false,true ,false,true>, cudaFuncAttributeMaxDynamicSharedMemorySize, GEMM_SMEM);
        cudaFuncSetAttribute(tc_gemm<false,true ,true ,false>, cudaFuncAttributeMaxDynamicSharedMemorySize, GEMM_SMEM);
        g_attr_done = true;
    }

    float *x, *u, *h1, *ffo, *t3, *lg;
    bf16 *xh, *xl, *qh, *ql, *kTh, *kTl, *vTh, *vTl, *Ph, *Pl, *M2h, *M2l;
    bf16 *h1h, *h1l, *t1h, *t1l, *h2h, *h2l;
    bf16 *WqTh, *WqTl, *WkTh, *WkTl, *WvTh, *WvTl, *WuTh, *WuTl;
    bf16 *W1Th, *W1Tl, *W2Th, *W2Tl, *W3Th, *W3Tl;
    cudaGetSymbolAddress((void**)&x,   g_x);
    cudaGetSymbolAddress((void**)&u,   g_u);
    cudaGetSymbolAddress((void**)&h1,  g_h1);
    cudaGetSymbolAddress((void**)&ffo, g_ffo);
    cudaGetSymbolAddress((void**)&t3,  g_t3);
    cudaGetSymbolAddress((void**)&lg,  g_lg);
    cudaGetSymbolAddress((void**)&xh,  g_xh);  cudaGetSymbolAddress((void**)&xl,  g_xl);
    cudaGetSymbolAddress((void**)&qh,  g_qh);  cudaGetSymbolAddress((void**)&ql,  g_ql);
    cudaGetSymbolAddress((void**)&kTh, g_kTh); cudaGetSymbolAddress((void**)&kTl, g_kTl);
    cudaGetSymbolAddress((void**)&vTh, g_vTh); cudaGetSymbolAddress((void**)&vTl, g_vTl);
    cudaGetSymbolAddress((void**)&Ph,  g_Ph);  cudaGetSymbolAddress((void**)&Pl,  g_Pl);
    cudaGetSymbolAddress((void**)&M2h, g_M2h); cudaGetSymbolAddress((void**)&M2l, g_M2l);
    cudaGetSymbolAddress((void**)&h1h, g_h1h); cudaGetSymbolAddress((void**)&h1l, g_h1l);
    cudaGetSymbolAddress((void**)&t1h, g_t1h); cudaGetSymbolAddress((void**)&t1l, g_t1l);
    cudaGetSymbolAddress((void**)&h2h, g_h2h); cudaGetSymbolAddress((void**)&h2l, g_h2l);
    cudaGetSymbolAddress((void**)&WqTh, g_WqTh); cudaGetSymbolAddress((void**)&WqTl, g_WqTl);
    cudaGetSymbolAddress((void**)&WkTh, g_WkTh); cudaGetSymbolAddress((void**)&WkTl, g_WkTl);
    cudaGetSymbolAddress((void**)&WvTh, g_WvTh); cudaGetSymbolAddress((void**)&WvTl, g_WvTl);
    cudaGetSymbolAddress((void**)&WuTh, g_WuTh); cudaGetSymbolAddress((void**)&WuTl, g_WuTl);
    cudaGetSymbolAddress((void**)&W1Th, g_W1Th); cudaGetSymbolAddress((void**)&W1Tl, g_W1Tl);
    cudaGetSymbolAddress((void**)&W2Th, g_W2Th); cudaGetSymbolAddress((void**)&W2Tl, g_W2Tl);
    cudaGetSymbolAddress((void**)&W3Th, g_W3Th); cudaGetSymbolAddress((void**)&W3Tl, g_W3Tl);

    // ---- weight prep: transpose + split ----
    dim3 tb(256);
    transpose_split_kernel<<<dim3(DM/32, DM/32), tb>>>(Wq, WqTh, WqTl, DM, DM);
    transpose_split_kernel<<<dim3(DM/32, DM/32), tb>>>(Wk, WkTh, WkTl, DM, DM);
    transpose_split_kernel<<<dim3(DM/32, DM/32), tb>>>(Wv, WvTh, WvTl, DM, DM);
    transpose_split_kernel<<<dim3(DM/32, DM/32), tb>>>(Wu, WuTh, WuTl, DM, DM);
    transpose_split_kernel<<<dim3(FF/32, DM/32), tb>>>(W1, W1Th, W1Tl, DM, FF);
    transpose_split_kernel<<<dim3(DM/32, FF/32), tb>>>(W2, W2Th, W2Tl, FF, DM);
    transpose_split_kernel<<<dim3(D_HALF/32, DM/32), tb>>>(W3, W3Th, W3Tl, DM, D_HALF);

    // ---- 1. x = emb[idx] + posenc ----
    embed_kernel<<<T_TOK, 256>>>(idx, emb, x, xh, xl);

    // ---- 2-4. Q/K/V projections ----
    tc_gemm<false,false,false,true><<<dim3(8,128,1), 256, GEMM_SMEM>>>(
        xh, xl, DM, 0, WqTh, WqTl, DM, 0, bq, 1.f,
        nullptr, qh, ql, DM, 0, 0, 0, 1, T_TOK, DM);
    tc_gemm<true,false,false,true><<<dim3(8,128,1), 256, GEMM_SMEM>>>(
        xh, xl, DM, 0, WkTh, WkTl, DM, 0, bk, 1.f,
        nullptr, kTh, kTl, 0, 0, N_SEQ, (size_t)DM*N_SEQ, N_SEQ, T_TOK, DM);
    tc_gemm<true,false,false,true><<<dim3(8,128,1), 256, GEMM_SMEM>>>(
        xh, xl, DM, 0, WvTh, WvTl, DM, 0, bv, 1.f,
        nullptr, vTh, vTl, 0, 0, N_SEQ, (size_t)DM*N_SEQ, N_SEQ, T_TOK, DM);

    // ---- 5. P[b] = K^T V ----
    tc_gemm<false,false,false,true><<<dim3(8,8,D_BATCH), 256, GEMM_SMEM>>>(
        kTh, kTl, N_SEQ, (size_t)DM*N_SEQ, vTh, vTl, N_SEQ, (size_t)DM*N_SEQ,
        nullptr, 1.f, nullptr, Ph, Pl, DM, (size_t)DM*DM, 0, 0, 1, DM, N_SEQ);

    // ---- 6. M2^T[b] = (P @ Wu)^T / 8 ----
    tc_gemm<true,false,false,true><<<dim3(8,8,D_BATCH), 256, GEMM_SMEM>>>(
        Ph, Pl, DM, (size_t)DM*DM, WuTh, WuTl, DM, 0,
        nullptr, 0.125f, nullptr, M2h, M2l, 0, 0, DM, (size_t)DM*DM, DM, DM, DM);

    // ---- 7. u = Q @ M2 + bu (fp32 out) ----
    tc_gemm<false,false,true,false><<<dim3(8,16,D_BATCH), 256, GEMM_SMEM>>>(
        qh, ql, DM, (size_t)N_SEQ*DM, M2h, M2l, DM, (size_t)DM*DM,
        bu, 1.f, u, nullptr, nullptr, DM, (size_t)N_SEQ*DM, 0, 0, 1, N_SEQ, DM);

    // ---- 8. h1 = LN(x + u) ----
    add_ln_kernel<<<T_TOK, 256>>>(x, u, g1, be1, h1, h1h, h1l);

    // ---- 9. t1 = relu(h1 @ W1 + b1) ----
    tc_gemm<false,true,false,true><<<dim3(32,128,1), 256, GEMM_SMEM>>>(
        h1h, h1l, DM, 0, W1Th, W1Tl, DM, 0, b1, 1.f,
        nullptr, t1h, t1l, FF, 0, 0, 0, 1, T_TOK, DM);

    // ---- 10. ffo = t1 @ W2 + b2 (fp32 out) ----
    tc_gemm<false,false,true,false><<<dim3(8,128,1), 256, GEMM_SMEM>>>(
        t1h, t1l, FF, 0, W2Th, W2Tl, FF, 0, b2, 1.f,
        ffo, nullptr, nullptr, DM, 0, 0, 0, 1, T_TOK, FF);

    // ---- 11. h2 = LN(h1 + ffo) ----
    add_ln_kernel<<<T_TOK, 256>>>(h1, ffo, g2, be2, nullptr, h2h, h2l);

    // ---- 12. t3 = relu(h2 @ W3 + b3) (fp32 out) ----
    tc_gemm<false,true,true,false><<<dim3(4,128,1), 256, GEMM_SMEM>>>(
        h2h, h2l, DM, 0, W3Th, W3Tl, DM, 0, b3, 1.f,
        t3, nullptr, nullptr, D_HALF, 0, 0, 0, 1, T_TOK, DM);

    // ---- 13. logits = t3 @ W4 + b4 (fp32 SGEMM, N=75) ----
    sgemm_small_n<<<dim3(1, T_TOK/BM, 1), 256>>>(t3, W4, b4, lg,
                                                 T_TOK, NCAT, D_HALF, D_HALF, NCAT, NCAT);

    // ---- 14. out = sigmoid(LN(logits)) ----
    final_kernel<<<T_TOK/8, 256>>>(lg, g3, be3, out);
}